// round 1
// baseline (speedup 1.0000x reference)
#include <cuda_runtime.h>
#include <cstdint>

// ---------------------------------------------------------------------------
// GAT hierarchical 2-layer, restructured:
//   e_s = x_self  @ P_s   (P_s[h] = W[:,hD:(h+1)D] @ a_s[h])
//   e_n = x_neigh @ P_n
//   alpha = softmax_E(leaky_relu(e_s + e_n, 0.2))
//   y[h] = sum_e alpha[e,h] * x_neigh[e]      (aggregate RAW features)
//   out[h*D:(h+1)*D] = y[h] @ W[:,hD:(h+1)D]  (GEMM after aggregation)
// This removes the per-neighbor projection (42 GF -> ~2.3 GF of GEMM +
// one streaming pass over each neighbor tensor).
// ---------------------------------------------------------------------------

#define NHEADS 4

// scratch layout (floats)
static constexpr size_t OFF_Y1   = 0;                       // [10240,4,128]
static constexpr size_t OFF_H1P  = OFF_Y1   + 10240ull*512; // [10240,512]
static constexpr size_t OFF_Y0   = OFF_H1P  + 10240ull*512; // [1024,4,128]
static constexpr size_t OFF_H0P  = OFF_Y0   + 1024ull*512;  // [1024,512]
static constexpr size_t OFF_Y2   = OFF_H0P  + 1024ull*512;  // [1024,4,512]
static constexpr size_t OFF_H0PP = OFF_Y2   + 1024ull*2048; // [1024,512]
static constexpr size_t OFF_P    = OFF_H0PP + 1024ull*512;  // P0s,P0n,P1s,P1n
static constexpr size_t SCRATCH_FLOATS = OFF_P + 5120;

__device__ float g_scratch[SCRATCH_FLOATS];

// ---------------------------------------------------------------------------
// Precompute P vectors: P[h*F+f] = sum_d W[f, h*128+d] * a[h,d]
// layout in P area: [0,512) P0s | [512,1024) P0n | [1024,3072) P1s | [3072,5120) P1n
// ---------------------------------------------------------------------------
__global__ void prep_kernel(const float* __restrict__ W0,
                            const float* __restrict__ a0s,
                            const float* __restrict__ a0n,
                            const float* __restrict__ W1,
                            const float* __restrict__ a1s,
                            const float* __restrict__ a1n,
                            float* __restrict__ P)
{
    int t = blockIdx.x * blockDim.x + threadIdx.x;
    if (t < 512) {                       // layer0: F=128, HID=512
        int h = t >> 7, f = t & 127;
        float s = 0.f, n = 0.f;
        const float* wrow = W0 + (size_t)f * 512 + h * 128;
        const float* as = a0s + h * 128;
        const float* an = a0n + h * 128;
        #pragma unroll 4
        for (int d = 0; d < 128; d++) {
            float wv = wrow[d];
            s = fmaf(wv, as[d], s);
            n = fmaf(wv, an[d], n);
        }
        P[t] = s;
        P[512 + t] = n;
    } else if (t < 512 + 2048) {         // layer1: F=512, HID=512
        int i = t - 512;
        int h = i >> 9, f = i & 511;
        float s = 0.f, n = 0.f;
        const float* wrow = W1 + (size_t)f * 512 + h * 128;
        const float* as = a1s + h * 128;
        const float* an = a1n + h * 128;
        #pragma unroll 4
        for (int d = 0; d < 128; d++) {
            float wv = wrow[d];
            s = fmaf(wv, as[d], s);
            n = fmaf(wv, an[d], n);
        }
        P[1024 + i] = s;
        P[1024 + 2048 + i] = n;
    }
}

// ---------------------------------------------------------------------------
// Attention + raw-feature aggregation. One block (128 threads) per group.
//   xs: [G,F] self, xn: [G,E,F] neighbors, Ps/Pn: [4,F], y: [G,4,F]
// ---------------------------------------------------------------------------
template<int F, int E>
__global__ __launch_bounds__(128)
void attn_kernel(const float* __restrict__ xs,
                 const float* __restrict__ xn,
                 const float* __restrict__ Ps,
                 const float* __restrict__ Pn,
                 float* __restrict__ y)
{
    constexpr int H = NHEADS;
    const int g    = blockIdx.x;
    const int tid  = threadIdx.x;
    const int w    = tid >> 5;     // warp id == head id (exactly 4 warps)
    const int lane = tid & 31;

    __shared__ float sxn[E * F];
    __shared__ float sxs[F];
    __shared__ float slog[E * H];
    __shared__ float salpha[E * H];

    const float* gxn = xn + (size_t)g * (E * F);
    for (int i = tid; i < E * F; i += 128) sxn[i] = gxn[i];
    const float* gxs = xs + (size_t)g * F;
    for (int i = tid; i < F; i += 128) sxs[i] = gxs[i];
    __syncthreads();

    // preload this head's Pn slice into registers
    constexpr int PR = F / 32;
    float pn[PR];
    #pragma unroll
    for (int i = 0; i < PR; i++) pn[i] = Pn[w * F + lane + 32 * i];

    // e_s (one dot per head, done by the head's warp)
    float es = 0.f;
    #pragma unroll
    for (int i = 0; i < PR; i++)
        es = fmaf(sxs[lane + 32 * i], Ps[w * F + lane + 32 * i], es);
    #pragma unroll
    for (int o = 16; o; o >>= 1) es += __shfl_down_sync(0xffffffffu, es, o);
    es = __shfl_sync(0xffffffffu, es, 0);

    // e_n per neighbor, leaky_relu(e_s + e_n)
    for (int e = 0; e < E; e++) {
        float acc = 0.f;
        #pragma unroll
        for (int i = 0; i < PR; i++)
            acc = fmaf(sxn[e * F + lane + 32 * i], pn[i], acc);
        #pragma unroll
        for (int o = 16; o; o >>= 1) acc += __shfl_down_sync(0xffffffffu, acc, o);
        if (lane == 0) {
            float l = es + acc;
            slog[e * H + w] = (l >= 0.f) ? l : 0.2f * l;
        }
    }
    __syncwarp();

    // softmax over E within the warp (E <= 32)
    {
        float v = (lane < E) ? slog[lane * H + w] : -3.4e38f;
        float m = v;
        #pragma unroll
        for (int o = 16; o; o >>= 1) m = fmaxf(m, __shfl_xor_sync(0xffffffffu, m, o));
        float p = (lane < E) ? __expf(v - m) : 0.f;
        float s = p;
        #pragma unroll
        for (int o = 16; o; o >>= 1) s += __shfl_xor_sync(0xffffffffu, s, o);
        if (lane < E) salpha[lane * H + w] = p / s;
    }
    __syncthreads();

    // y[h][f] = sum_e alpha[e,h] * xn[e][f]; thread t covers columns t, t+128,...
    constexpr int C = F / 128;
    float acc[C][H];
    #pragma unroll
    for (int c = 0; c < C; c++)
        #pragma unroll
        for (int h = 0; h < H; h++) acc[c][h] = 0.f;

    for (int e = 0; e < E; e++) {
        float al[H];
        #pragma unroll
        for (int h = 0; h < H; h++) al[h] = salpha[e * H + h];
        #pragma unroll
        for (int c = 0; c < C; c++) {
            float v = sxn[e * F + c * 128 + tid];
            #pragma unroll
            for (int h = 0; h < H; h++) acc[c][h] = fmaf(al[h], v, acc[c][h]);
        }
    }
    float* gy = y + (size_t)g * (H * F);
    #pragma unroll
    for (int h = 0; h < H; h++)
        #pragma unroll
        for (int c = 0; c < C; c++)
            gy[h * F + c * 128 + tid] = acc[c][h];
}

// ---------------------------------------------------------------------------
// Simple fp32 tiled GEMM: C = A @ B. 64x64 tile, BK=16, 256 threads, 4x4/thread.
// Requires M%64==0, N%64==0, K%16==0, 16B-aligned tiles (true for all calls).
// Batched via blockIdx.z with element offsets (per-head slices).
// ---------------------------------------------------------------------------
__global__ __launch_bounds__(256)
void gemm_kernel(const float* __restrict__ A, const float* __restrict__ B,
                 float* __restrict__ C,
                 int K, int lda, int ldb, int ldc,
                 int offA, int offB, int offC)
{
    A += (size_t)blockIdx.z * offA;
    B += (size_t)blockIdx.z * offB;
    C += (size_t)blockIdx.z * offC;

    const int row0 = blockIdx.y * 64;
    const int col0 = blockIdx.x * 64;
    const int tx = threadIdx.x;       // 0..15
    const int ty = threadIdx.y;       // 0..15
    const int tid = ty * 16 + tx;

    __shared__ float As[16][64];
    __shared__ float Bs[16][64];

    const int ar = tid >> 2;          // 0..63
    const int ac = (tid & 3) * 4;     // 0,4,8,12
    const int br = tid >> 4;          // 0..15
    const int bc = (tid & 15) * 4;    // 0..60

    float acc[4][4];
    #pragma unroll
    for (int i = 0; i < 4; i++)
        #pragma unroll
        for (int j = 0; j < 4; j++) acc[i][j] = 0.f;

    for (int k0 = 0; k0 < K; k0 += 16) {
        float4 av = *(const float4*)(A + (size_t)(row0 + ar) * lda + k0 + ac);
        As[ac + 0][ar] = av.x;
        As[ac + 1][ar] = av.y;
        As[ac + 2][ar] = av.z;
        As[ac + 3][ar] = av.w;
        float4 bv = *(const float4*)(B + (size_t)(k0 + br) * ldb + col0 + bc);
        *(float4*)&Bs[br][bc] = bv;
        __syncthreads();

        #pragma unroll
        for (int k = 0; k < 16; k++) {
            float4 a4 = *(const float4*)&As[k][ty * 4];
            float4 b4 = *(const float4*)&Bs[k][tx * 4];
            float a[4] = {a4.x, a4.y, a4.z, a4.w};
            float b[4] = {b4.x, b4.y, b4.z, b4.w};
            #pragma unroll
            for (int i = 0; i < 4; i++)
                #pragma unroll
                for (int j = 0; j < 4; j++)
                    acc[i][j] = fmaf(a[i], b[j], acc[i][j]);
        }
        __syncthreads();
    }

    #pragma unroll
    for (int i = 0; i < 4; i++) {
        float4 o = {acc[i][0], acc[i][1], acc[i][2], acc[i][3]};
        *(float4*)(C + (size_t)(row0 + ty * 4 + i) * ldc + col0 + tx * 4) = o;
    }
}

// ---------------------------------------------------------------------------
// launch
// ---------------------------------------------------------------------------
extern "C" void kernel_launch(void* const* d_in, const int* in_sizes, int n_in,
                              void* d_out, int out_size)
{
    const float* h0  = (const float*)d_in[0];   // [1024,128]
    const float* h1  = (const float*)d_in[1];   // [1024,10,128]
    const float* h2  = (const float*)d_in[2];   // [1024,250,128]
    const float* W0  = (const float*)d_in[3];   // [128,512]
    const float* a0s = (const float*)d_in[4];
    const float* a0n = (const float*)d_in[5];
    const float* W1  = (const float*)d_in[6];   // [512,512]
    const float* a1s = (const float*)d_in[7];
    const float* a1n = (const float*)d_in[8];
    const float* Wfc = (const float*)d_in[9];   // [512,256]
    float* out = (float*)d_out;                 // [1024,256]

    float* scr = nullptr;
    cudaGetSymbolAddress((void**)&scr, g_scratch);
    float* y1   = scr + OFF_Y1;
    float* h1p  = scr + OFF_H1P;
    float* y0   = scr + OFF_Y0;
    float* h0p  = scr + OFF_H0P;
    float* y2   = scr + OFF_Y2;
    float* h0pp = scr + OFF_H0PP;
    float* P    = scr + OFF_P;

    dim3 tpb(16, 16);

    // P vectors
    prep_kernel<<<10, 256>>>(W0, a0s, a0n, W1, a1s, a1n, P);

    // layer0, level1: self=h1 [10240,128], neigh=h2 [10240,25,128] -> y1
    attn_kernel<128, 25><<<10240, 128>>>(h1, h2, P, P + 512, y1);
    // layer0, level0: self=h0 [1024,128], neigh=h1 [1024,10,128] -> y0
    attn_kernel<128, 10><<<1024, 128>>>(h0, h1, P, P + 512, y0);

    // h1' = per-head y1 @ W0_h : [10240,128]x[128,128], 4 heads
    gemm_kernel<<<dim3(2, 160, 4), tpb>>>(y1, W0, h1p, 128, 512, 512, 512, 128, 128, 128);
    // h0' = per-head y0 @ W0_h : [1024,128]x[128,128], 4 heads
    gemm_kernel<<<dim3(2, 16, 4), tpb>>>(y0, W0, h0p, 128, 512, 512, 512, 128, 128, 128);

    // layer1, level0: self=h0' [1024,512], neigh=h1' [1024,10,512] -> y2
    attn_kernel<512, 10><<<1024, 128>>>(h0p, h1p, P + 1024, P + 3072, y2);

    // h0'' = per-head y2 @ W1_h : [1024,512]x[512,128], 4 heads
    gemm_kernel<<<dim3(2, 16, 4), tpb>>>(y2, W1, h0pp, 512, 2048, 512, 512, 512, 128, 128);

    // final: out = h0'' @ Wfc : [1024,512]x[512,256]
    gemm_kernel<<<dim3(4, 16, 1), tpb>>>(h0pp, Wfc, out, 512, 512, 256, 256, 0, 0, 0);
}